// round 9
// baseline (speedup 1.0000x reference)
#include <cuda_runtime.h>

#define NB   64
#define HIN  480
#define WIN  80
#define C0   8
#define C1   16
#define C2   16
#define C3   32
#define H2   160
#define W2   40
#define TT   40
#define IG   640
#define HID  256
#define G3   768

// ---------------- device scratch ----------------
__device__ float g_tmp0[NB*C0*HIN*WIN];   // conv0 out (relu)
__device__ float g_tmp1[NB*C1*H2*W2];     // pool(relu(conv1))
__device__ float g_tmp2[NB*C2*H2*W2];     // relu(conv2)
__device__ float g_x[NB*TT*IG];           // GRU input (b,t,640)
__device__ float g_gx[2*TT*NB*G3];        // gate preacts, both dirs
__device__ float g_h[2][2*NB*HID];        // double-buffered hidden

// packed fp32x2 FMA, scalar broadcast on 2nd operand
__device__ __forceinline__ float2 ffma2(float2 w, float x, float2 c) {
    float2 r;
    asm("{\n\t"
        ".reg .b64 wa, xb, cc, dd;\n\t"
        "mov.b64 wa, {%2,%3};\n\t"
        "mov.b64 xb, {%4,%4};\n\t"
        "mov.b64 cc, {%5,%6};\n\t"
        "fma.rn.f32x2 dd, wa, xb, cc;\n\t"
        "mov.b64 {%0,%1}, dd;\n\t"
        "}" : "=f"(r.x), "=f"(r.y)
            : "f"(w.x), "f"(w.y), "f"(x), "f"(c.x), "f"(c.y));
    return r;
}
// packed fp32x2 FMA, both operands vectors
__device__ __forceinline__ float2 ffma2p(float2 a, float2 b, float2 c) {
    float2 r;
    asm("{\n\t"
        ".reg .b64 aa, bb2, cc, dd;\n\t"
        "mov.b64 aa, {%2,%3};\n\t"
        "mov.b64 bb2, {%4,%5};\n\t"
        "mov.b64 cc, {%6,%7};\n\t"
        "fma.rn.f32x2 dd, aa, bb2, cc;\n\t"
        "mov.b64 {%0,%1}, dd;\n\t"
        "}" : "=f"(r.x), "=f"(r.y)
            : "f"(a.x), "f"(a.y), "f"(b.x), "f"(b.y), "f"(c.x), "f"(c.y));
    return r;
}
__device__ __forceinline__ float2 fmax2(float2 a, float2 b) {
    return make_float2(fmaxf(a.x,b.x), fmaxf(a.y,b.y));
}

// ---------------- prep: copy h0 ----------------
__global__ void k_prep(const float* __restrict__ hidden) {
    int i = blockIdx.x*256 + threadIdx.x;
    if (i < 2*NB*HID) g_h[0][i] = hidden[i];
}

// ---------------- conv0: 1->8, 3x3 pad1, relu ----------------
__global__ __launch_bounds__(256) void k_conv0(const float* __restrict__ in,
                                               const float* __restrict__ w,
                                               const float* __restrict__ bias) {
    __shared__ float2 sw[36];
    __shared__ float2 sb[4];
    int tid = threadIdx.x;
    if (tid < 36) { int ocp = tid/9, k = tid%9;
        sw[tid] = make_float2(w[(2*ocp)*9+k], w[(2*ocp+1)*9+k]); }
    if (tid < 4) sb[tid] = make_float2(bias[2*tid], bias[2*tid+1]);
    __syncthreads();
    int gid = blockIdx.x*256 + tid;
    int x = gid % WIN; int y = (gid/WIN) % HIN; int b = gid/(WIN*HIN);
    const float* ip = in + (size_t)b*HIN*WIN;
    float v[9];
#pragma unroll
    for (int dy=0; dy<3; dy++)
#pragma unroll
    for (int dx=0; dx<3; dx++) {
        int yy = y+dy-1, xx = x+dx-1;
        v[dy*3+dx] = (yy>=0 && yy<HIN && xx>=0 && xx<WIN) ? ip[yy*WIN+xx] : 0.f;
    }
#pragma unroll
    for (int ocp=0; ocp<4; ocp++) {
        float2 acc = sb[ocp];
#pragma unroll
        for (int k=0;k<9;k++) acc = ffma2(sw[ocp*9+k], v[k], acc);
        g_tmp0[((b*C0 + 2*ocp  )*HIN + y)*WIN + x] = fmaxf(acc.x, 0.f);
        g_tmp0[((b*C0 + 2*ocp+1)*HIN + y)*WIN + x] = fmaxf(acc.y, 0.f);
    }
}

// ------- conv1 (8->16) + relu + maxpool(3x2) — 4px sliding window -------
// block 240 = 20 colgroups(4 conv cols) x 12 conv rows; tile = 4 pool rows
__global__ __launch_bounds__(240) void k_conv1pool(const float* __restrict__ w,
                                                   const float* __restrict__ bias) {
    extern __shared__ float smx[];
    float*  s_in   = smx;                       // 8 x 14 x 82 = 9184
    float2* s_w    = (float2*)(smx + 9184);     // 576
    float2* s_b    = s_w + 576;                 // 8
    float2* s_part = s_b + 8;                   // 12*40*8 = 3840
    int tid = threadIdx.x;
    int b = blockIdx.x/40, tileP = blockIdx.x%40;
    for (int i=tid; i<576; i+=240) {
        int ocp = i/72, rem = i%72;
        s_w[i] = make_float2(w[(2*ocp)*72+rem], w[(2*ocp+1)*72+rem]);
    }
    if (tid<8) s_b[tid] = make_float2(bias[2*tid], bias[2*tid+1]);
    int r0g = tileP*12 - 1;
    for (int i=tid; i<9184; i+=240) {
        int ic = i/1148; int rem = i%1148; int r = rem/82, c = rem%82;
        int ih = r0g + r, iw = c - 1;
        float v = 0.f;
        if (ih>=0 && ih<HIN && iw>=0 && iw<WIN)
            v = g_tmp0[((b*C0+ic)*HIN+ih)*WIN+iw];
        s_in[i] = v;
    }
    __syncthreads();
    int cg = tid % 20;                 // conv cols 4cg..4cg+3
    int row = tid / 20;                // 0..11
    float2 acc[4][8];
#pragma unroll
    for (int p=0;p<4;p++)
#pragma unroll
    for (int o=0;o<8;o++) acc[p][o] = s_b[o];
#pragma unroll 1
    for (int ic=0; ic<8; ic++) {
        const float* sp = s_in + ic*1148;
#pragma unroll
        for (int dy=0; dy<3; dy++) {
            const float2* xp = (const float2*)(sp + (row+dy)*82 + 4*cg);
            float2 xa = xp[0], xb2 = xp[1], xc = xp[2];
            float xs[6] = {xa.x, xa.y, xb2.x, xb2.y, xc.x, xc.y};
#pragma unroll
            for (int dx=0; dx<3; dx++) {
                float2 wv[8];
#pragma unroll
                for (int o=0;o<8;o++) wv[o] = s_w[o*72 + ic*9 + dy*3 + dx];
#pragma unroll
                for (int p=0;p<4;p++)
#pragma unroll
                for (int o=0;o<8;o++)
                    acc[p][o] = ffma2(wv[o], xs[dx+p], acc[p][o]);
            }
        }
    }
#pragma unroll
    for (int pcl=0; pcl<2; pcl++)
#pragma unroll
    for (int o=0;o<8;o++)
        s_part[(row*40 + 2*cg + pcl)*8 + o] = fmax2(acc[2*pcl][o], acc[2*pcl+1][o]);
    __syncthreads();
    for (int i=tid; i<1280; i+=240) {
        int o = i%8; int pcol = (i/8)%40; int pr = i/320;   // pr 0..3
        float2 m = s_part[((3*pr  )*40 + pcol)*8 + o];
        m = fmax2(m, s_part[((3*pr+1)*40 + pcol)*8 + o]);
        m = fmax2(m, s_part[((3*pr+2)*40 + pcol)*8 + o]);
        int oh = tileP*4 + pr;
        g_tmp1[((b*C1 + 2*o  )*H2 + oh)*W2 + pcol] = fmaxf(m.x, 0.f);
        g_tmp1[((b*C1 + 2*o+1)*H2 + oh)*W2 + pcol] = fmaxf(m.y, 0.f);
    }
}

// ---------------- conv2: 16->16, 3x3 pad1, relu — 4px sliding window ----------
// block 320 = 10 cg x 32 rows; grid = 64 x 5
__global__ __launch_bounds__(320) void k_conv2(const float* __restrict__ w,
                                               const float* __restrict__ bias) {
    extern __shared__ float smx[];
    float*  s_in = smx;                         // 16 x 34 x 42 = 22848
    float2* s_w  = (float2*)(smx + 22848);      // 1152
    float2* s_b  = s_w + 1152;                  // 8
    int tid = threadIdx.x;
    int b = blockIdx.x/5, tile = blockIdx.x%5;
    for (int i=tid; i<1152; i+=320) {
        int ocp = i/144, rem = i%144;
        s_w[i] = make_float2(w[(2*ocp)*144+rem], w[(2*ocp+1)*144+rem]);
    }
    if (tid<8) s_b[tid] = make_float2(bias[2*tid], bias[2*tid+1]);
    int r0g = tile*32 - 1;
    for (int i=tid; i<22848; i+=320) {
        int ic = i/1428; int rem = i%1428; int r = rem/42, c = rem%42;
        int ih = r0g + r, iw = c - 1;
        float v = 0.f;
        if (ih>=0 && ih<H2 && iw>=0 && iw<W2)
            v = g_tmp1[((b*C1+ic)*H2+ih)*W2+iw];
        s_in[i] = v;
    }
    __syncthreads();
    int cg = tid % 10;                 // conv cols 4cg..4cg+3
    int row = tid / 10;                // 0..31
    float2 acc[4][8];
#pragma unroll
    for (int p=0;p<4;p++)
#pragma unroll
    for (int o=0;o<8;o++) acc[p][o] = s_b[o];
#pragma unroll 1
    for (int ic=0; ic<16; ic++) {
        const float* sp = s_in + ic*1428;
#pragma unroll
        for (int dy=0; dy<3; dy++) {
            const float2* xp = (const float2*)(sp + (row+dy)*42 + 4*cg);
            float2 xa = xp[0], xb2 = xp[1], xc = xp[2];
            float xs[6] = {xa.x, xa.y, xb2.x, xb2.y, xc.x, xc.y};
#pragma unroll
            for (int dx=0; dx<3; dx++) {
                float2 wv[8];
#pragma unroll
                for (int o=0;o<8;o++) wv[o] = s_w[o*144 + ic*9 + dy*3 + dx];
#pragma unroll
                for (int p=0;p<4;p++)
#pragma unroll
                for (int o=0;o<8;o++)
                    acc[p][o] = ffma2(wv[o], xs[dx+p], acc[p][o]);
            }
        }
    }
    int oh = tile*32 + row;
#pragma unroll
    for (int o=0;o<8;o++)
#pragma unroll
    for (int p=0;p<4;p++) {
        int ow = 4*cg + p;
        g_tmp2[((b*C2 + 2*o  )*H2 + oh)*W2 + ow] = fmaxf(acc[p][o].x, 0.f);
        g_tmp2[((b*C2 + 2*o+1)*H2 + oh)*W2 + ow] = fmaxf(acc[p][o].y, 0.f);
    }
}

// ---- conv3 (16->32) + relu + maxpool(4x2) -> GRU layout, 4px window ----
// block 320 = 10 cg x 16 rows x 2 ocg; tile = 4 pool rows; grid = 64 x 10
__global__ __launch_bounds__(320) void k_conv3pool(const float* __restrict__ w,
                                                   const float* __restrict__ bias) {
    extern __shared__ float smx[];
    float*  s_in   = smx;                       // 16 x 18 x 42 = 12096
    float2* s_w    = (float2*)(smx + 12096);    // 2304
    float2* s_b    = s_w + 2304;                // 16
    float2* s_part = s_b + 16;                  // 16*20*16 = 5120
    int tid = threadIdx.x;
    int b = blockIdx.x/10, tile = blockIdx.x%10;
    for (int i=tid; i<2304; i+=320) {
        int ocp = i/144, rem = i%144;
        s_w[i] = make_float2(w[(2*ocp)*144+rem], w[(2*ocp+1)*144+rem]);
    }
    if (tid<16) s_b[tid] = make_float2(bias[2*tid], bias[2*tid+1]);
    int r0g = tile*16 - 1;
    for (int i=tid; i<12096; i+=320) {
        int ic = i/756; int rem = i%756; int r = rem/42, c = rem%42;
        int ih = r0g + r, iw = c - 1;
        float v = 0.f;
        if (ih>=0 && ih<H2 && iw>=0 && iw<W2)
            v = g_tmp2[((b*C2+ic)*H2+ih)*W2+iw];
        s_in[i] = v;
    }
    __syncthreads();
    {
        int cg  = tid % 10;            // conv cols 4cg..4cg+3
        int row = (tid/10) % 16;       // 0..15
        int ocg = tid / 160;           // 0..1
        float2 acc[4][8];
#pragma unroll
        for (int p=0;p<4;p++)
#pragma unroll
        for (int o=0;o<8;o++) acc[p][o] = s_b[ocg*8+o];
#pragma unroll 1
        for (int ic=0; ic<16; ic++) {
            const float* sp = s_in + ic*756;
#pragma unroll
            for (int dy=0; dy<3; dy++) {
                const float2* xp = (const float2*)(sp + (row+dy)*42 + 4*cg);
                float2 xa = xp[0], xb2 = xp[1], xc = xp[2];
                float xs[6] = {xa.x, xa.y, xb2.x, xb2.y, xc.x, xc.y};
#pragma unroll
                for (int dx=0; dx<3; dx++) {
                    float2 wv[8];
#pragma unroll
                    for (int o=0;o<8;o++) wv[o] = s_w[(ocg*8+o)*144 + ic*9 + dy*3 + dx];
#pragma unroll
                    for (int p=0;p<4;p++)
#pragma unroll
                    for (int o=0;o<8;o++)
                        acc[p][o] = ffma2(wv[o], xs[dx+p], acc[p][o]);
                }
            }
        }
#pragma unroll
        for (int pcl=0; pcl<2; pcl++)
#pragma unroll
        for (int o=0;o<8;o++)
            s_part[(row*20 + 2*cg + pcl)*16 + ocg*8 + o]
                = fmax2(acc[2*pcl][o], acc[2*pcl+1][o]);
    }
    __syncthreads();
    for (int i=tid; i<1280; i+=320) {
        int o = i%16; int pcol = (i/16)%20; int pr = i/320;   // pr 0..3
        float2 m = s_part[((4*pr  )*20 + pcol)*16 + o];
        m = fmax2(m, s_part[((4*pr+1)*20 + pcol)*16 + o]);
        m = fmax2(m, s_part[((4*pr+2)*20 + pcol)*16 + o]);
        m = fmax2(m, s_part[((4*pr+3)*20 + pcol)*16 + o]);
        int t = tile*4 + pr;
        *(float2*)(g_x + (size_t)(b*TT + t)*IG + pcol*32 + 2*o)
            = make_float2(fmaxf(m.x,0.f), fmaxf(m.y,0.f));
    }
}

// -------- gx GEMM: (2560 x 1536) = x @ W_ih^T + b_ih, double-buffered --------
__global__ __launch_bounds__(256) void k_gemm(const float* __restrict__ wf,
                                              const float* __restrict__ wb,
                                              const float* __restrict__ bf,
                                              const float* __restrict__ bb) {
    __shared__ float As[2][16*132];
    __shared__ float Bs[2][16*68];
    int tid = threadIdx.x;
    int bm = blockIdx.x % 20, bn = blockIdx.x / 20;
    int m0 = bm*128, n0 = bn*64;
    int d = (n0 >= 768) ? 1 : 0;
    const float* wsrc = d ? wb : wf;
    const float* bsrc = d ? bb : bf;
    int g0 = n0 - d*768;
    int tx = tid%16, ty = tid/16;
    float2 acc[8][2];
#pragma unroll
    for (int i=0;i<8;i++)
#pragma unroll
    for (int j=0;j<2;j++) acc[i][j] = make_float2(0.f, 0.f);

    // addressing constants for the cooperative loads
    int rowA0 = (tid      )>>2, k4A0 = (tid      )&3;
    int rowA1 = (tid + 256)>>2, k4A1 = (tid + 256)&3;
    int nB = tid>>2, k4B = tid&3;
    int mA0 = m0 + rowA0; int tA0 = mA0>>6, bA0 = mA0&63;
    int mA1 = m0 + rowA1; int tA1 = mA1>>6, bA1 = mA1&63;
    const float* pA0 = g_x + (size_t)(bA0*TT + tA0)*IG + k4A0*4;
    const float* pA1 = g_x + (size_t)(bA1*TT + tA1)*IG + k4A1*4;
    const float* pB  = wsrc + (size_t)(g0+nB)*IG + k4B*4;

    float4 ra0 = *(const float4*)(pA0);
    float4 ra1 = *(const float4*)(pA1);
    float4 rb  = *(const float4*)(pB);
#pragma unroll
    for (int kt=0; kt<40; kt++) {
        int cur = kt & 1;
        // store prefetched regs into current buffer
        As[cur][(k4A0*4+0)*132 + rowA0] = ra0.x;
        As[cur][(k4A0*4+1)*132 + rowA0] = ra0.y;
        As[cur][(k4A0*4+2)*132 + rowA0] = ra0.z;
        As[cur][(k4A0*4+3)*132 + rowA0] = ra0.w;
        As[cur][(k4A1*4+0)*132 + rowA1] = ra1.x;
        As[cur][(k4A1*4+1)*132 + rowA1] = ra1.y;
        As[cur][(k4A1*4+2)*132 + rowA1] = ra1.z;
        As[cur][(k4A1*4+3)*132 + rowA1] = ra1.w;
        Bs[cur][(k4B*4+0)*68 + nB] = rb.x;
        Bs[cur][(k4B*4+1)*68 + nB] = rb.y;
        Bs[cur][(k4B*4+2)*68 + nB] = rb.z;
        Bs[cur][(k4B*4+3)*68 + nB] = rb.w;
        __syncthreads();
        if (kt < 39) {
            int k0 = (kt+1)*16;
            ra0 = *(const float4*)(pA0 + k0);
            ra1 = *(const float4*)(pA1 + k0);
            rb  = *(const float4*)(pB  + k0);
        }
#pragma unroll
        for (int k=0;k<16;k++) {
            float4 a0 = *(const float4*)(&As[cur][k*132 + ty*8]);
            float4 a1 = *(const float4*)(&As[cur][k*132 + ty*8 + 4]);
            float4 bv = *(const float4*)(&Bs[cur][k*68 + tx*4]);
            float2 b01 = make_float2(bv.x, bv.y);
            float2 b23 = make_float2(bv.z, bv.w);
            float av[8] = {a0.x,a0.y,a0.z,a0.w,a1.x,a1.y,a1.z,a1.w};
#pragma unroll
            for (int i=0;i<8;i++) {
                acc[i][0] = ffma2(b01, av[i], acc[i][0]);
                acc[i][1] = ffma2(b23, av[i], acc[i][1]);
            }
        }
        __syncthreads();
    }
#pragma unroll
    for (int i=0;i<8;i++) {
        int m = m0 + ty*8 + i; int t = m>>6; int bb_ = m&63;
        float4 ov;
        ov.x = acc[i][0].x + bsrc[g0 + tx*4 + 0];
        ov.y = acc[i][0].y + bsrc[g0 + tx*4 + 1];
        ov.z = acc[i][1].x + bsrc[g0 + tx*4 + 2];
        ov.w = acc[i][1].y + bsrc[g0 + tx*4 + 3];
        *(float4*)(g_gx + (size_t)((d*TT + t)*NB + bb_)*G3 + g0 + tx*4) = ov;
    }
}

// -------- persistent bidirectional GRU: W_hh in registers, cluster barrier ----
// 128 blocks = 16 clusters of 8; CTA = hidden slice (32 units); 384 thr =
// 96 gate-rows x 4 k-quarters. Each thread holds 64 floats of W_hh in regs.
__global__ __launch_bounds__(384) __cluster_dims__(8,1,1)
void k_gru(const float* __restrict__ whf,
           const float* __restrict__ whb,
           const float* __restrict__ bhf,
           const float* __restrict__ bhb,
           float* __restrict__ out) {
    __shared__ float h_s[8*264];         // swizzled: f4 index j*4+q for k4=q*16+j
    __shared__ float gh_s[8*96];
    __shared__ float bhh_s[96];
    int tid = threadIdx.x;
    int bx = blockIdx.x;
    int s     = bx & 7;                  // cluster rank = hidden slice
    int group = bx >> 3;
    int d     = group >> 3;
    int bgrp  = group & 7;
    const float* whh = d ? whb : whf;
    const float* bhh = d ? bhb : bhf;

    int q = tid & 3;                     // k-quarter (64 floats)
    int r = tid >> 2;                    // gate row 0..95
    int c = r >> 5, u = r & 31;
    int grow = c*256 + s*32 + u;

    float4 wreg[16];
#pragma unroll
    for (int j=0;j<16;j++)
        wreg[j] = *(const float4*)(whh + (size_t)grow*256 + q*64 + j*4);
    for (int i=tid; i<96; i+=384) {
        int cc = i>>5, uu = i&31;
        bhh_s[i] = bhh[cc*256 + s*32 + uu];
    }
    __syncthreads();

    int b0 = bgrp*8;

    for (int step=0; step<40; step++) {
        int p = step & 1;
        int t = d ? (39 - step) : step;

        // prefetch gx for epilogue
        float pre0=0.f, pre1=0.f, pre2=0.f;
        if (tid < 256) {
            int bi = tid>>5, uu = tid&31;
            const float* gx = g_gx + (size_t)((d*TT + t)*NB + b0 + bi)*G3 + s*32 + uu;
            pre0 = __ldcg(gx);
            pre1 = __ldcg(gx + 256);
            pre2 = __ldcg(gx + 512);
        }

        // load h (swizzled) into smem
        const float* hsrc = g_h[p] + (size_t)(d*NB + b0)*HID;
        for (int i=tid; i<512; i+=384) {
            int bi = i>>6, k4 = i&63;
            int jj = k4 & 15, qq = k4 >> 4;
            float4 v = __ldcg((const float4*)(hsrc + bi*HID + k4*4));
            *(float4*)(h_s + bi*264 + (jj*4 + qq)*4) = v;
        }
        __syncthreads();

        // dot: each thread, its 64-float quarter vs 8 batches
        float2 acc[8];
#pragma unroll
        for (int b=0;b<8;b++) acc[b] = make_float2(0.f, 0.f);
#pragma unroll
        for (int j=0;j<16;j++) {
            float4 wv = wreg[j];
            float2 wlo = make_float2(wv.x, wv.y);
            float2 whi = make_float2(wv.z, wv.w);
#pragma unroll
            for (int b=0;b<8;b++) {
                float4 hv = *(const float4*)(h_s + b*264 + (j*4 + q)*4);
                acc[b] = ffma2p(wlo, make_float2(hv.x, hv.y), acc[b]);
                acc[b] = ffma2p(whi, make_float2(hv.z, hv.w), acc[b]);
            }
        }
        // quad reduce across k-quarters (lanes 4r+q)
#pragma unroll
        for (int b=0;b<8;b++) {
            float s1 = acc[b].x + acc[b].y;
            s1 += __shfl_xor_sync(0xffffffffu, s1, 1);
            s1 += __shfl_xor_sync(0xffffffffu, s1, 2);
            if (q == 0) gh_s[b*96 + r] = s1;
        }
        __syncthreads();

        // epilogue on 256 threads
        if (tid < 256) {
            int bi = tid>>5, uu = tid&31;
            float hr = gh_s[bi*96      + uu] + bhh_s[uu];
            float hz = gh_s[bi*96 + 32 + uu] + bhh_s[32+uu];
            float hn = gh_s[bi*96 + 64 + uu] + bhh_s[64+uu];
            int k = s*32 + uu;                        // hidden unit index
            int jj = (k>>2) & 15, qq = k>>6, ee = k&3;
            float hold = h_s[bi*264 + (jj*4 + qq)*4 + ee];
            float rg = 1.f/(1.f + expf(-(pre0+hr)));
            float zg = 1.f/(1.f + expf(-(pre1+hz)));
            float ng = tanhf(pre2 + rg*hn);
            float hnew = (1.f - zg)*ng + zg*hold;
            g_h[p^1][(size_t)(d*NB + b0 + bi)*HID + k] = hnew;
            out[((size_t)(b0+bi)*TT + t)*512 + d*256 + k] = hnew;
            if (step == 39)
                out[(size_t)NB*TT*512 + (size_t)(d*NB + b0 + bi)*HID + k] = hnew;
        }
        __threadfence();
        asm volatile("barrier.cluster.arrive.aligned;" ::: "memory");
        asm volatile("barrier.cluster.wait.aligned;"  ::: "memory");
    }
}

// ---------------- launcher ----------------
extern "C" void kernel_launch(void* const* d_in, const int* in_sizes, int n_in,
                              void* d_out, int out_size) {
    const float* img  = (const float*)d_in[0];
    const float* hid  = (const float*)d_in[1];
    const float* c0w  = (const float*)d_in[2];
    const float* c0b  = (const float*)d_in[3];
    const float* c1w  = (const float*)d_in[4];
    const float* c1b  = (const float*)d_in[5];
    const float* c2w  = (const float*)d_in[6];
    const float* c2b  = (const float*)d_in[7];
    const float* c3w  = (const float*)d_in[8];
    const float* c3b  = (const float*)d_in[9];
    const float* wihf = (const float*)d_in[10];
    const float* whhf = (const float*)d_in[11];
    const float* bihf = (const float*)d_in[12];
    const float* bhhf = (const float*)d_in[13];
    const float* wihb = (const float*)d_in[14];
    const float* whhb = (const float*)d_in[15];
    const float* bihb = (const float*)d_in[16];
    const float* bhhb = (const float*)d_in[17];
    float* out = (float*)d_out;

    const int CONV1_SMEM = 9184*4 + (576+8+3840)*8;          // 72128
    const int CONV2_SMEM = 22848*4 + (1152+8)*8;             // 100672
    const int CONV3_SMEM = 12096*4 + (2304+16+5120)*8;       // 107904
    cudaFuncSetAttribute(k_conv1pool, cudaFuncAttributeMaxDynamicSharedMemorySize, CONV1_SMEM);
    cudaFuncSetAttribute(k_conv2, cudaFuncAttributeMaxDynamicSharedMemorySize, CONV2_SMEM);
    cudaFuncSetAttribute(k_conv3pool, cudaFuncAttributeMaxDynamicSharedMemorySize, CONV3_SMEM);

    k_prep<<<128, 256>>>(hid);
    k_conv0<<<NB*HIN*WIN/256, 256>>>(img, c0w, c0b);
    k_conv1pool<<<NB*40, 240, CONV1_SMEM>>>(c1w, c1b);
    k_conv2<<<NB*5, 320, CONV2_SMEM>>>(c2w, c2b);
    k_conv3pool<<<NB*10, 320, CONV3_SMEM>>>(c3w, c3b);
    k_gemm<<<480, 256>>>(wihf, wihb, bihf, bihb);
    k_gru<<<128, 384>>>(whhf, whhb, bhhf, bhhb, out);
}